// round 13
// baseline (speedup 1.0000x reference)
#include <cuda_runtime.h>
#include <cuda_fp16.h>

#define NB 128
#define NB3 (NB * NB * NB)

// Window table, z fastest, x duplicated into the entry:
//   W[cell=(ix*NB+iy)*NB+iz] = 32B = 2 x uint4:
//     chunk0 = { G(ix,  iy,iz), G(ix,  iy+1,iz) }  (y-pair at x0)  4ch fp16 each
//     chunk1 = { G(ix+1,iy,iz), G(ix+1,iy+1,iz) }  (y-pair at x1)
//   (iy+1, ix+1 clamped at 127 during build.)
// A point's 8 corners = entries iz0 and iz0+1 = ONE contiguous 64B window
// -> 1.25 cache lines per point on average.
// +4 uint4 pad: the iz0=127 window overruns one entry with zero weight (fz=0).
__device__ uint4 g_win[NB3 * 2 + 4];

__device__ __forceinline__ uint4 pack_ypair(float4 a, float4 b)
{
    __half2 h0 = __floats2half2_rn(a.x, a.y);
    __half2 h1 = __floats2half2_rn(a.z, a.w);
    __half2 h2 = __floats2half2_rn(b.x, b.y);
    __half2 h3 = __floats2half2_rn(b.z, b.w);
    uint4 v;
    v.x = *reinterpret_cast<const unsigned int*>(&h0);
    v.y = *reinterpret_cast<const unsigned int*>(&h1);
    v.z = *reinterpret_cast<const unsigned int*>(&h2);
    v.w = *reinterpret_cast<const unsigned int*>(&h3);
    return v;
}

// No transpose: natural-order reads (4 row streams, L2-reused 4x) and fully
// coalesced 32B/thread writes.
__global__ __launch_bounds__(256)
void build_win_kernel(const float4* __restrict__ grid)
{
    int idx = blockIdx.x * blockDim.x + threadIdx.x;
    if (idx >= NB3) return;

    int iy = (idx >> 7) & (NB - 1);
    int ix = idx >> 14;
    int dy = (iy < NB - 1) ? NB : 0;
    int dx = (ix < NB - 1) ? (NB * NB) : 0;

    float4 a00 = grid[idx];             // (x0,y0)
    float4 a01 = grid[idx + dy];        // (x0,y1)
    float4 a10 = grid[idx + dx];        // (x1,y0)
    float4 a11 = grid[idx + dx + dy];   // (x1,y1)

    g_win[2 * idx + 0] = pack_ypair(a00, a01);
    g_win[2 * idx + 1] = pack_ypair(a10, a11);
}

// evict_last policy for the pinned table gathers
__device__ __forceinline__ unsigned long long make_evict_last_policy()
{
    unsigned long long pol;
    asm("createpolicy.fractional.L2::evict_last.b64 %0, 1.0;" : "=l"(pol));
    return pol;
}

__device__ __forceinline__ uint4 ldg_pin(const uint4* p, unsigned long long pol)
{
    uint4 v;
    asm("ld.global.nc.L2::cache_hint.v4.u32 {%0,%1,%2,%3}, [%4], %5;"
        : "=r"(v.x), "=r"(v.y), "=r"(v.z), "=r"(v.w)
        : "l"(p), "l"(pol));
    return v;
}

// y-lerp of one 16B chunk (2 corners x 4ch fp16)
__device__ __forceinline__ float4 ylerp(uint4 p, float wy0, float wy1)
{
    float2 axy = __half22float2(*reinterpret_cast<const __half2*>(&p.x));
    float2 azw = __half22float2(*reinterpret_cast<const __half2*>(&p.y));
    float2 bxy = __half22float2(*reinterpret_cast<const __half2*>(&p.z));
    float2 bzw = __half22float2(*reinterpret_cast<const __half2*>(&p.w));

    float4 r;
    r.x = fmaf(wy1, bxy.x, wy0 * axy.x);
    r.y = fmaf(wy1, bxy.y, wy0 * axy.y);
    r.z = fmaf(wy1, bzw.x, wy0 * azw.x);
    r.w = fmaf(wy1, bzw.y, wy0 * azw.y);
    return r;
}

struct PSetup {
    int  u4;        // this lane's 16B chunk: 2*cell + l
    float fy, wv;   // wv = wx(xs) * wz(zs)
};

__device__ __forceinline__ PSetup make_setup(float px, float py, float pz,
                                             int xs, int zs, int l)
{
    px = fminf(fmaxf(px * (float)NB, 0.0f), (float)(NB - 1));
    py = fminf(fmaxf(py * (float)NB, 0.0f), (float)(NB - 1));
    pz = fminf(fmaxf(pz * (float)NB, 0.0f), (float)(NB - 1));

    int ix0 = (int)floorf(px);
    int iy0 = (int)floorf(py);
    int iz0 = (int)floorf(pz);

    float fx = px - (float)ix0;
    float fz = pz - (float)iz0;

    PSetup s;
    s.fy = py - (float)iy0;
    float wx = xs ? fx : (1.0f - fx);
    float wz = zs ? fz : (1.0f - fz);
    s.wv = wx * wz;

    int cell = (ix0 * NB + iy0) * NB + iz0;
    s.u4 = 2 * cell + l;   // l = 2*zs+xs: chunks of the contiguous 64B window
    return s;
}

// Weighted partial + 2-stage butterfly: lane l (xs=l&1, zs=l>>1) ends with
// channel 2*xs+zs summed over the 4 lanes of the point group.
__device__ __forceinline__ float finish(uint4 A, const PSetup& s, int xs, int zs)
{
    float wy1 = s.fy, wy0 = 1.0f - s.fy;
    float4 m = ylerp(A, wy0, wy1);
    float4 r;
    r.x = s.wv * m.x;
    r.y = s.wv * m.y;
    r.z = s.wv * m.z;
    r.w = s.wv * m.w;

    // stage 1 (xor 1, combine over x): xs=0 keeps ch{0,1}, xs=1 keeps ch{2,3}
    float v0 = xs ? r.x : r.z;
    float v1 = xs ? r.y : r.w;
    float t0 = __shfl_xor_sync(0xFFFFFFFFu, v0, 1);
    float t1 = __shfl_xor_sync(0xFFFFFFFFu, v1, 1);
    float s0 = (xs ? r.z : r.x) + t0;   // channel 2*xs
    float s1 = (xs ? r.w : r.y) + t1;   // channel 2*xs+1

    // stage 2 (xor 2, combine over z): zs=0 keeps s0, zs=1 keeps s1
    float v2 = zs ? s0 : s1;
    float t2 = __shfl_xor_sync(0xFFFFFFFFu, v2, 2);
    return (zs ? s1 : s0) + t2;         // channel 2*xs + zs
}

// 4 lanes per point, 2 points per thread (p, p+h): ONE LDG.128 per point,
// window = 1.25 lines avg.
__global__ __launch_bounds__(256)
void interp_win_kernel(const float* __restrict__ x,
                       float* __restrict__ out,   // [N,4] flat floats
                       int n, int h)
{
    int tid = blockIdx.x * blockDim.x + threadIdx.x;
    int l   = tid & 3;
    int p0  = tid >> 2;
    int xs  = l & 1;
    int zs  = l >> 1;

    bool v0 = (p0 < h);
    int c0 = v0 ? p0 : 0;
    int p1 = c0 + h;
    bool v1 = v0 && (p1 < n);
    int c1 = v1 ? p1 : c0;

    unsigned long long pol = make_evict_last_policy();

    // Streaming coord loads (4 lanes of a group read the same addresses ->
    // they coalesce to the same sectors; evict-first keeps table pinned).
    float ax = __ldcs(&x[3 * c0 + 0]);
    float ay = __ldcs(&x[3 * c0 + 1]);
    float az = __ldcs(&x[3 * c0 + 2]);
    float bx = __ldcs(&x[3 * c1 + 0]);
    float by = __ldcs(&x[3 * c1 + 1]);
    float bz = __ldcs(&x[3 * c1 + 2]);

    PSetup S0 = make_setup(ax, ay, az, xs, zs, l);
    PSetup S1 = make_setup(bx, by, bz, xs, zs, l);

    // Two pinned gathers back-to-back; each 4-lane group covers one 64B window.
    uint4 A0 = ldg_pin(&g_win[S0.u4], pol);
    uint4 A1 = ldg_pin(&g_win[S1.u4], pol);

    float o0 = finish(A0, S0, xs, zs);
    float o1 = finish(A1, S1, xs, zs);

    int ch = 2 * xs + zs;   // permutation within the point's 16B out segment
    if (v0) __stcs(&out[4 * p0 + ch], o0);
    if (v1) __stcs(&out[4 * p1 + ch], o1);
}

extern "C" void kernel_launch(void* const* d_in, const int* in_sizes, int n_in,
                              void* d_out, int out_size)
{
    const float*  x    = (const float*)d_in[0];   // [N,3] float32
    const float4* grid = (const float4*)d_in[1];  // [128,128,128,4] float32
    float*        out  = (float*)d_out;           // [N,4] float32

    int n = in_sizes[0] / 3;
    int h = (n + 1) / 2;

    const int block = 256;
    build_win_kernel<<<(NB3 + block - 1) / block, block>>>(grid);

    long long threads = 4LL * h;
    int grid_dim = (int)((threads + block - 1) / block);
    interp_win_kernel<<<grid_dim, block>>>(x, out, n, h);
}

// round 14
// speedup vs baseline: 1.2222x; 1.2222x over previous
#include <cuda_runtime.h>
#include <cuda_fp16.h>

#define NB 128
#define NJ (NB / 2)
#define NENT (NJ * NB * NB)   // 1,048,576 entries

// x-dedup pair table: entry (j, iy, iz), 32B = 2 x uint4:
//   u4[0] = { G(2j,  iy,iz), G(2j,  iy+1,iz) }   (y-pair at x=2j)   4ch fp16 each
//   u4[1] = { G(2j+1,iy,iz), G(2j+1,iy+1,iz) }   (y-pair at x=2j+1)
// iz fastest (entry stride 32B): the z-pair of a point is 2 adjacent entries.
// Size = 64*128*128*32B = 33.5MB -> L2-resident (x-dedup makes the x-pair free).
// ix0 even: all 8 corners in ONE contiguous 64B window (1.25 lines avg).
// ix0 odd:  two 48B-span windows at j and j+1 (2.5 lines avg). Overall 1.875/pt.
__device__ uint4 g_xdp[NENT * 2 + 4];

__device__ __forceinline__ uint4 pack_ypair(float4 a, float4 b)
{
    __half2 h0 = __floats2half2_rn(a.x, a.y);
    __half2 h1 = __floats2half2_rn(a.z, a.w);
    __half2 h2 = __floats2half2_rn(b.x, b.y);
    __half2 h3 = __floats2half2_rn(b.z, b.w);
    uint4 v;
    v.x = *reinterpret_cast<const unsigned int*>(&h0);
    v.y = *reinterpret_cast<const unsigned int*>(&h1);
    v.z = *reinterpret_cast<const unsigned int*>(&h2);
    v.w = *reinterpret_cast<const unsigned int*>(&h3);
    return v;
}

// One thread per entry: coalesced reads along iz, coalesced 32B writes.
__global__ __launch_bounds__(256)
void build_xdp_kernel(const float4* __restrict__ grid)
{
    int idx = blockIdx.x * blockDim.x + threadIdx.x;
    if (idx >= NENT) return;

    int iz = idx & (NB - 1);
    int iy = (idx >> 7) & (NB - 1);
    int j  = idx >> 14;

    int x0 = 2 * j;
    int x1 = 2 * j + 1;
    int iyp = min(iy + 1, NB - 1);

    float4 a0 = grid[(x0 * NB + iy)  * NB + iz];
    float4 a1 = grid[(x0 * NB + iyp) * NB + iz];
    float4 b0 = grid[(x1 * NB + iy)  * NB + iz];
    float4 b1 = grid[(x1 * NB + iyp) * NB + iz];

    g_xdp[2 * idx + 0] = pack_ypair(a0, a1);
    g_xdp[2 * idx + 1] = pack_ypair(b0, b1);
}

// y-lerp of one 16B chunk (2 corners x 4ch fp16)
__device__ __forceinline__ float4 ylerp(uint4 p, float wy0, float wy1)
{
    float2 axy = __half22float2(*reinterpret_cast<const __half2*>(&p.x));
    float2 azw = __half22float2(*reinterpret_cast<const __half2*>(&p.y));
    float2 bxy = __half22float2(*reinterpret_cast<const __half2*>(&p.z));
    float2 bzw = __half22float2(*reinterpret_cast<const __half2*>(&p.w));

    float4 r;
    r.x = fmaf(wy1, bxy.x, wy0 * axy.x);
    r.y = fmaf(wy1, bxy.y, wy0 * axy.y);
    r.z = fmaf(wy1, bzw.x, wy0 * azw.x);
    r.w = fmaf(wy1, bzw.y, wy0 * azw.y);
    return r;
}

struct PSetup {
    int  u4;        // this lane's 16B chunk index
    float fy, wv;   // wv = wx(xs) * wz(zs)
};

__device__ __forceinline__ PSetup make_setup(float px, float py, float pz,
                                             int xs, int zs)
{
    px = fminf(fmaxf(px * (float)NB, 0.0f), (float)(NB - 1));
    py = fminf(fmaxf(py * (float)NB, 0.0f), (float)(NB - 1));
    pz = fminf(fmaxf(pz * (float)NB, 0.0f), (float)(NB - 1));

    int ix0 = (int)floorf(px);
    int iy0 = (int)floorf(py);
    int iz0 = (int)floorf(pz);

    float fx = px - (float)ix0;
    float fz = pz - (float)iz0;

    PSetup s;
    s.fy = py - (float)iy0;
    float wx = xs ? fx : (1.0f - fx);
    float wz = zs ? fz : (1.0f - fz);
    s.wv = wx * wz;

    int x  = min(ix0 + xs, NB - 1);   // clamp: duplicate chunk has zero weight
    int iz = min(iz0 + zs, NB - 1);

    // chunk = entry(j=x>>1, iy0, iz) * 2 + (x & 1)
    s.u4 = (((x >> 1) * NB + iy0) * NB + iz) * 2 + (x & 1);
    return s;
}

// Weighted partial + 2-stage butterfly: lane l=2*zs+xs ends with channel
// 2*xs+zs summed over the 4 lanes of the point group. (Verified in R13.)
__device__ __forceinline__ float finish(uint4 A, const PSetup& s, int xs, int zs)
{
    float wy1 = s.fy, wy0 = 1.0f - s.fy;
    float4 m = ylerp(A, wy0, wy1);
    float4 r;
    r.x = s.wv * m.x;
    r.y = s.wv * m.y;
    r.z = s.wv * m.z;
    r.w = s.wv * m.w;

    // stage 1 (xor 1, combine over x): xs=0 keeps ch{0,1}, xs=1 keeps ch{2,3}
    float v0 = xs ? r.x : r.z;
    float v1 = xs ? r.y : r.w;
    float t0 = __shfl_xor_sync(0xFFFFFFFFu, v0, 1);
    float t1 = __shfl_xor_sync(0xFFFFFFFFu, v1, 1);
    float s0 = (xs ? r.z : r.x) + t0;   // channel 2*xs
    float s1 = (xs ? r.w : r.y) + t1;   // channel 2*xs+1

    // stage 2 (xor 2, combine over z): zs=0 keeps s0, zs=1 keeps s1
    float v2 = zs ? s0 : s1;
    float t2 = __shfl_xor_sync(0xFFFFFFFFu, v2, 2);
    return (zs ? s1 : s0) + t2;         // channel 2*xs + zs
}

// 4 lanes per point, 2 points per thread (p, p+h): 2 gathers in flight,
// 1.875 lines per point average.
__global__ __launch_bounds__(256)
void interp_xdp_kernel(const float* __restrict__ x,
                       float* __restrict__ out,   // [N,4] flat floats
                       int n, int h)
{
    int tid = blockIdx.x * blockDim.x + threadIdx.x;
    int l   = tid & 3;
    int p0  = tid >> 2;
    int xs  = l & 1;
    int zs  = l >> 1;

    bool v0 = (p0 < h);
    int c0 = v0 ? p0 : 0;
    int p1 = c0 + h;
    bool v1 = v0 && (p1 < n);
    int c1 = v1 ? p1 : c0;

    // Streaming coord loads (quad lanes broadcast the same sectors).
    float ax = __ldcs(&x[3 * c0 + 0]);
    float ay = __ldcs(&x[3 * c0 + 1]);
    float az = __ldcs(&x[3 * c0 + 2]);
    float bx = __ldcs(&x[3 * c1 + 0]);
    float by = __ldcs(&x[3 * c1 + 1]);
    float bz = __ldcs(&x[3 * c1 + 2]);

    PSetup S0 = make_setup(ax, ay, az, xs, zs);
    PSetup S1 = make_setup(bx, by, bz, xs, zs);

    // Two gathers back-to-back (L2-only, random into the 33.5MB table).
    uint4 A0 = __ldcg(&g_xdp[S0.u4]);
    uint4 A1 = __ldcg(&g_xdp[S1.u4]);

    float o0 = finish(A0, S0, xs, zs);
    float o1 = finish(A1, S1, xs, zs);

    int ch = 2 * xs + zs;   // permutation within the point's 16B out segment
    if (v0) __stcs(&out[4 * p0 + ch], o0);
    if (v1) __stcs(&out[4 * p1 + ch], o1);
}

extern "C" void kernel_launch(void* const* d_in, const int* in_sizes, int n_in,
                              void* d_out, int out_size)
{
    const float*  x    = (const float*)d_in[0];   // [N,3] float32
    const float4* grid = (const float4*)d_in[1];  // [128,128,128,4] float32
    float*        out  = (float*)d_out;           // [N,4] float32

    int n = in_sizes[0] / 3;
    int h = (n + 1) / 2;

    const int block = 256;
    build_xdp_kernel<<<(NENT + block - 1) / block, block>>>(grid);

    long long threads = 4LL * h;
    int grid_dim = (int)((threads + block - 1) / block);
    interp_xdp_kernel<<<grid_dim, block>>>(x, out, n, h);
}

// round 15
// speedup vs baseline: 1.3255x; 1.0845x over previous
#include <cuda_runtime.h>
#include <cuda_fp16.h>

#define NB 128
#define NJ (NB / 2)
#define NENT (NJ * NB * NB)   // 1,048,576 entries of 32B = 33.5 MB

// x-dedup pair table: entry (j, iy, iz) = 32B = 2 x 16B chunks:
//   chunk b = { G(2j+b, iy, iz), G(2j+b, iy+1, iz) }  (y-pair, 4ch fp16 each)
// iz fastest (entry stride 32B). chunk index c = entry*2 + b.
// A point's 4 chunks: (x0,z0),(x1,z0),(x0,z1),(x1,z1);
//   ix0 even -> all 4 in one 64B window (1.25 lines avg)
//   ix0 odd  -> windows at j and j+1      (2.5 lines avg)   => 1.875 lines/pt.
__device__ uint4 g_xdp[NENT * 2];

__device__ __forceinline__ uint4 pack_ypair(float4 a, float4 b)
{
    __half2 h0 = __floats2half2_rn(a.x, a.y);
    __half2 h1 = __floats2half2_rn(a.z, a.w);
    __half2 h2 = __floats2half2_rn(b.x, b.y);
    __half2 h3 = __floats2half2_rn(b.z, b.w);
    uint4 v;
    v.x = *reinterpret_cast<const unsigned int*>(&h0);
    v.y = *reinterpret_cast<const unsigned int*>(&h1);
    v.z = *reinterpret_cast<const unsigned int*>(&h2);
    v.w = *reinterpret_cast<const unsigned int*>(&h3);
    return v;
}

// One thread per 16B chunk: writes perfectly coalesced; reads form two
// coalesced row streams (x even / x odd) like the R12 build.
__global__ __launch_bounds__(256)
void build_xdp_kernel(const float4* __restrict__ grid)
{
    int c = blockIdx.x * blockDim.x + threadIdx.x;
    if (c >= NENT * 2) return;

    int b  = c & 1;
    int t  = c >> 1;
    int iz = t & (NB - 1);
    int iy = (t >> 7) & (NB - 1);
    int j  = t >> 14;

    int x   = 2 * j + b;
    int iyp = min(iy + 1, NB - 1);

    float4 a0 = grid[(x * NB + iy)  * NB + iz];
    float4 a1 = grid[(x * NB + iyp) * NB + iz];

    g_xdp[c] = pack_ypair(a0, a1);
}

// y-lerp of one 16B chunk (2 corners x 4ch fp16)
__device__ __forceinline__ float4 ylerp(uint4 p, float wy0, float wy1)
{
    float2 axy = __half22float2(*reinterpret_cast<const __half2*>(&p.x));
    float2 azw = __half22float2(*reinterpret_cast<const __half2*>(&p.y));
    float2 bxy = __half22float2(*reinterpret_cast<const __half2*>(&p.z));
    float2 bzw = __half22float2(*reinterpret_cast<const __half2*>(&p.w));

    float4 r;
    r.x = fmaf(wy1, bxy.x, wy0 * axy.x);
    r.y = fmaf(wy1, bxy.y, wy0 * axy.y);
    r.z = fmaf(wy1, bzw.x, wy0 * azw.x);
    r.w = fmaf(wy1, bzw.y, wy0 * azw.y);
    return r;
}

struct Setup {
    int c0, c1;        // chunk indices for x0, x1 at this lane's z-slice
    float fx, fy, wz;  // wz = this lane's z weight
};

__device__ __forceinline__ Setup make_setup(float px, float py, float pz, int q)
{
    px = fminf(fmaxf(px * (float)NB, 0.0f), (float)(NB - 1));
    py = fminf(fmaxf(py * (float)NB, 0.0f), (float)(NB - 1));
    pz = fminf(fmaxf(pz * (float)NB, 0.0f), (float)(NB - 1));

    int ix0 = (int)floorf(px);
    int iy0 = (int)floorf(py);
    int iz0 = (int)floorf(pz);

    Setup s;
    s.fx = px - (float)ix0;
    s.fy = py - (float)iy0;
    float fz = pz - (float)iz0;
    s.wz = q ? fz : (1.0f - fz);

    int ix1 = min(ix0 + 1, NB - 1);
    int izq = min(iz0 + q, NB - 1);

    // chunk(x, izq) = (((x>>1)*NB + iy0)*NB + izq)*2 + (x&1)
    int rowq = iy0 * NB + izq;
    s.c0 = (((ix0 >> 1) * NB * NB + rowq) << 1) + (ix0 & 1);
    s.c1 = (((ix1 >> 1) * NB * NB + rowq) << 1) + (ix1 & 1);
    return s;
}

// Partial result for this lane's z-slice (all 4 channels, weighted by wz).
__device__ __forceinline__ float4 lane_partial(uint4 A, uint4 B, const Setup& s)
{
    float wy1 = s.fy, wy0 = 1.0f - s.fy;
    float4 m0 = ylerp(A, wy0, wy1);
    float4 m1 = ylerp(B, wy0, wy1);

    float wx1 = s.fx, wx0 = 1.0f - s.fx;
    float4 r;
    r.x = s.wz * fmaf(wx1, m1.x, wx0 * m0.x);
    r.y = s.wz * fmaf(wx1, m1.y, wx0 * m0.y);
    r.z = s.wz * fmaf(wx1, m1.z, wx0 * m0.z);
    r.w = s.wz * fmaf(wx1, m1.w, wx0 * m0.w);
    return r;
}

// Half-exchange: lane0 finalizes {x,y}, lane1 finalizes {z,w}; 2 shfls/point.
__device__ __forceinline__ float2 reduce_half(float4 r, int q)
{
    float s1 = __shfl_xor_sync(0xFFFFFFFFu, q ? r.x : r.z, 1);
    float s2 = __shfl_xor_sync(0xFFFFFFFFu, q ? r.y : r.w, 1);
    float2 o;
    if (q == 0) { o.x = r.x + s1; o.y = r.y + s2; }
    else        { o.x = r.z + s1; o.y = r.w + s2; }
    return o;
}

// 2 lanes per point, 2 points per lane-pair (p and p+half) -> 4 gathers in
// flight per thread, 1.875 distinct lines per point.
__global__ __launch_bounds__(256)
void interp_coop2_kernel(const float* __restrict__ x,
                         float2* __restrict__ out,   // [N,4] viewed as float2[2N]
                         int n, int half)
{
    int tid = blockIdx.x * blockDim.x + threadIdx.x;
    int p0  = tid >> 1;
    int q   = tid & 1;

    if (p0 >= half) return;
    int p1 = p0 + half;
    bool hasB = (p1 < n);
    int p1c = hasB ? p1 : p0;

    // Streaming loads for the point coords (touched once).
    float ax = __ldcs(&x[3 * p0 + 0]);
    float ay = __ldcs(&x[3 * p0 + 1]);
    float az = __ldcs(&x[3 * p0 + 2]);
    float bx = __ldcs(&x[3 * p1c + 0]);
    float by = __ldcs(&x[3 * p1c + 1]);
    float bz = __ldcs(&x[3 * p1c + 2]);

    Setup SA = make_setup(ax, ay, az, q);
    Setup SB = make_setup(bx, by, bz, q);

    // 4 gathers back-to-back (L2-only). Per instruction the lane pair's
    // addresses are one 32B entry apart -> 1.25 lines; even-ix0 points share
    // the same 64B window across both instructions.
    uint4 A0 = __ldcg(&g_xdp[SA.c0]);
    uint4 A1 = __ldcg(&g_xdp[SA.c1]);
    uint4 B0 = __ldcg(&g_xdp[SB.c0]);
    uint4 B1 = __ldcg(&g_xdp[SB.c1]);

    float4 ra = lane_partial(A0, A1, SA);
    float4 rb = lane_partial(B0, B1, SB);

    float2 oa = reduce_half(ra, q);
    float2 ob = reduce_half(rb, q);

    __stcs(&out[2 * p0 + q], oa);          // streaming store, pair writes 16B
    if (hasB)
        __stcs(&out[2 * p1 + q], ob);
}

extern "C" void kernel_launch(void* const* d_in, const int* in_sizes, int n_in,
                              void* d_out, int out_size)
{
    const float*  x    = (const float*)d_in[0];   // [N,3] float32
    const float4* grid = (const float4*)d_in[1];  // [128,128,128,4] float32
    float2*       out  = (float2*)d_out;          // [N,4] float32

    int n = in_sizes[0] / 3;
    int half = (n + 1) / 2;

    const int block = 256;
    build_xdp_kernel<<<(NENT * 2 + block - 1) / block, block>>>(grid);

    long long threads = 2LL * half;
    int grid_dim = (int)((threads + block - 1) / block);
    interp_coop2_kernel<<<grid_dim, block>>>(x, out, n, half);
}